// round 10
// baseline (speedup 1.0000x reference)
#include <cuda_runtime.h>

// Problem: B=4, T=4096, WINDOW=1024, MAX_DISP=2.0
// out[b,t] = linear interp of x at s = w[b]*coeff[t] + t (tent kernel collapses),
// out-of-range k dropped.
//
// CONVERGED FINAL FORM — latency-bound at the single-launch floor
// (all ncu pipes <0.5%, DRAM 0.1%). Mechanisms, each verified by measurement:
//  - grid=32 x 128: one block-wide x tile serves all 4 batch rows
//  - w (float4) load overlapped with the w-independent cooperative tile
//    prefetch: the two cold-DRAM round trips run concurrently (R2's -0.8us)
//  - fully branchless epilogue: FSEL weight masks enforce the exact k in [0,T)
//    semantics; clamped smem indices guarantee memory safety unconditionally
//  - coeff folded to a single bit-exact FFMA-imm; stores issued per-chain

#define T_DIM 4096
#define B_DIM 4
#define BLK   128                // t-range per block = 128; 32 blocks total
#define HALO  64                 // |w*coeff| << 64 for these inputs
#define TILE  (BLK + 2 * HALO)   // 256 floats = 1 KB shared

__global__ void __launch_bounds__(BLK) tvp_kernel(const float4* __restrict__ w4,
                                                  const float* __restrict__ x,
                                                  float* __restrict__ out) {
    __shared__ float sx[TILE];

    const int tid  = threadIdx.x;
    const int t    = blockIdx.x * BLK + tid;   // 0 .. T-1
    const int t0   = t - tid;                  // block's first t
    const int base = t0 - HALO;                // tile covers k in [base, base+TILE)

    // --- issue all independent loads up front (overlap) ---
    float4 wv = __ldg(w4);                     // all 4 w's, one 16B line, broadcast

    {   // cooperative x tile prefetch: 2 coalesced floats per thread, clamped
        int ca = min(max(base + tid,       0), T_DIM - 1);
        int cb = min(max(base + tid + BLK, 0), T_DIM - 1);
        float va = x[ca];                      // independent of w -> overlaps
        float vb = x[cb];
        sx[tid]       = va;
        sx[tid + BLK] = vb;
    }
    __syncthreads();

    // --- dependent math: 4 independent, fully branchless interp chains ---
    // coeff = 2*((t mod 1024)/1024 - 0.5) == (t mod 1024)/512 - 1, exact in fp32
    float wn = (float)(t & 1023);
    float c  = fmaf(wn, 1.0f / 512.0f, -1.0f); // single FFMA-imm, bit-exact
    float tf = (float)t;

    const float wb[4] = {wv.x, wv.y, wv.z, wv.w};

    #pragma unroll
    for (int b = 0; b < B_DIM; b++) {
        float s    = wb[b] * c + tf;           // match reference mul-then-add
        int   k0   = __float2int_rd(s);
        float frac = s - (float)k0;
        int   k1   = k0 + 1;

        // exact k-range enforcement via weight masks (FSEL, no branch)
        float m0 = (k0 >= 0 && k0 < T_DIM) ? (1.0f - frac) : 0.0f;
        float m1 = (k1 >= 0 && k1 < T_DIM) ? frac          : 0.0f;

        // tile reads with clamped smem index (always a valid address)
        int o0 = min(max(k0 - base, 0), TILE - 1);
        int o1 = min(max(k1 - base, 0), TILE - 1);

        // store as soon as this chain resolves (coalesced per warp)
        out[b * T_DIM + t] = fmaf(m0, sx[o0], m1 * sx[o1]);
    }
}

extern "C" void kernel_launch(void* const* d_in, const int* in_sizes, int n_in,
                              void* d_out, int out_size) {
    const float4* w4 = (const float4*)d_in[0];  // [4,1] -> one float4
    const float*  x  = (const float*)d_in[1];   // [1,4096]
    float* out = (float*)d_out;                 // [4,4096,1] = 16384 floats

    const int blocks = T_DIM / BLK;             // 32
    tvp_kernel<<<blocks, BLK>>>(w4, x, out);
}

// round 11
// speedup vs baseline: 1.0069x; 1.0069x over previous
#include <cuda_runtime.h>

// Problem: B=4, T=4096, WINDOW=1024, MAX_DISP=2.0
// out[b,t] = linear interp of x at s = w[b]*coeff[t] + t (tent kernel collapses),
// out-of-range k dropped.
//
// Latency-bound at the single-launch floor. Controlled experiment vs R10:
// warp-private x tiles (no block barrier, no cross-warp LDG dependency) at
// MATCHED instruction count — exactly 2 coalesced LDGs per lane, same
// branchless FSEL epilogue, same grid=32 x 128 batched-b shape.

#define T_DIM 4096
#define B_DIM 4
#define BLK   128                 // 4 warps/block; 32 blocks; t-range 128/block
#define WHALO 16                  // per-warp halo; |w*coeff| <= ~2.5 << 16
#define WTILE (32 + 2 * WHALO)    // 64 floats per warp -> 2 LDGs per lane

__global__ void __launch_bounds__(BLK) tvp_kernel(const float4* __restrict__ w4,
                                                  const float* __restrict__ x,
                                                  float* __restrict__ out) {
    __shared__ float sx[(BLK / 32) * WTILE];   // 256 floats, per-warp slices

    const int tid  = threadIdx.x;
    const int lane = tid & 31;
    const int t    = blockIdx.x * BLK + tid;   // 0 .. T-1
    const int base = (t - lane) - WHALO;       // warp tile covers [base, base+WTILE)
    float* stile   = &sx[(tid >> 5) * WTILE];

    // --- issue all independent loads up front (overlap) ---
    float4 wv = __ldg(w4);                     // all 4 w's, one 16B line, broadcast

    {   // warp-private tile prefetch: 2 coalesced floats per lane, clamped
        int ca = min(max(base + lane,      0), T_DIM - 1);
        int cb = min(max(base + lane + 32, 0), T_DIM - 1);
        float va = x[ca];                      // independent of w -> overlaps
        float vb = x[cb];
        stile[lane]      = va;
        stile[lane + 32] = vb;
    }
    __syncwarp();                              // no block barrier, no cross-warp wait

    // --- dependent math: 4 independent, fully branchless interp chains ---
    // coeff = 2*((t mod 1024)/1024 - 0.5) == (t mod 1024)/512 - 1, exact in fp32
    float wn = (float)(t & 1023);
    float c  = fmaf(wn, 1.0f / 512.0f, -1.0f); // single FFMA-imm, bit-exact
    float tf = (float)t;

    const float wb[4] = {wv.x, wv.y, wv.z, wv.w};

    #pragma unroll
    for (int b = 0; b < B_DIM; b++) {
        float s    = wb[b] * c + tf;           // match reference mul-then-add
        int   k0   = __float2int_rd(s);
        float frac = s - (float)k0;
        int   k1   = k0 + 1;

        // exact k-range enforcement via weight masks (FSEL, no branch)
        float m0 = (k0 >= 0 && k0 < T_DIM) ? (1.0f - frac) : 0.0f;
        float m1 = (k1 >= 0 && k1 < T_DIM) ? frac          : 0.0f;

        // tile reads with clamped smem index (always a valid address)
        int o0 = min(max(k0 - base, 0), WTILE - 1);
        int o1 = min(max(k1 - base, 0), WTILE - 1);

        // store as soon as this chain resolves (coalesced per warp)
        out[b * T_DIM + t] = fmaf(m0, stile[o0], m1 * stile[o1]);
    }
}

extern "C" void kernel_launch(void* const* d_in, const int* in_sizes, int n_in,
                              void* d_out, int out_size) {
    const float4* w4 = (const float4*)d_in[0];  // [4,1] -> one float4
    const float*  x  = (const float*)d_in[1];   // [1,4096]
    float* out = (float*)d_out;                 // [4,4096,1] = 16384 floats

    const int blocks = T_DIM / BLK;             // 32
    tvp_kernel<<<blocks, BLK>>>(w4, x, out);
}

// round 12
// speedup vs baseline: 1.0211x; 1.0141x over previous
#include <cuda_runtime.h>

// Problem: B=4, T=4096, WINDOW=1024, MAX_DISP=2.0
// out[b,t] = linear interp of x at s = w[b]*coeff[t] + t (tent kernel collapses),
// out-of-range k dropped.
//
// FINAL KERNEL — converged over 11 measured rounds; latency-bound at the
// single-launch floor (all ncu pipes <0.5%, DRAM 0.1%). Mechanisms, each
// verified by a predicted-delta experiment:
//  - analytic collapse of the [4,4096,4096] tent-kernel matmul to a 2-tap
//    linear interpolation (R1)
//  - w (float4) load overlapped with the w-independent cooperative x-tile
//    prefetch: the two cold-DRAM round trips run concurrently (R2, -0.8us)
//  - grid=32 x 128: one block-wide tile serves all 4 batch rows (R6)
//  - fully branchless epilogue: FSEL weight masks enforce exact k in [0,T)
//    semantics; clamped smem indices give unconditional memory safety (R7)
//  - coeff folded to one bit-exact FFMA-imm; per-chain stores (R8/R9)
// Controls: identical-source rerun bounded noise (R5); barrier scope shown
// irrelevant at matched instruction count (R11).

#define T_DIM 4096
#define B_DIM 4
#define BLK   128                // t-range per block = 128; 32 blocks total
#define HALO  64                 // |w*coeff| << 64 for these inputs
#define TILE  (BLK + 2 * HALO)   // 256 floats = 1 KB shared

__global__ void __launch_bounds__(BLK) tvp_kernel(const float4* __restrict__ w4,
                                                  const float* __restrict__ x,
                                                  float* __restrict__ out) {
    __shared__ float sx[TILE];

    const int tid  = threadIdx.x;
    const int t    = blockIdx.x * BLK + tid;   // 0 .. T-1
    const int t0   = t - tid;                  // block's first t
    const int base = t0 - HALO;                // tile covers k in [base, base+TILE)

    // --- issue all independent loads up front (overlap) ---
    float4 wv = __ldg(w4);                     // all 4 w's, one 16B line, broadcast

    {   // cooperative x tile prefetch: 2 coalesced floats per thread, clamped
        int ca = min(max(base + tid,       0), T_DIM - 1);
        int cb = min(max(base + tid + BLK, 0), T_DIM - 1);
        float va = x[ca];                      // independent of w -> overlaps
        float vb = x[cb];
        sx[tid]       = va;
        sx[tid + BLK] = vb;
    }
    __syncthreads();

    // --- dependent math: 4 independent, fully branchless interp chains ---
    // coeff = 2*((t mod 1024)/1024 - 0.5) == (t mod 1024)/512 - 1, exact in fp32
    float wn = (float)(t & 1023);
    float c  = fmaf(wn, 1.0f / 512.0f, -1.0f); // single FFMA-imm, bit-exact
    float tf = (float)t;

    const float wb[4] = {wv.x, wv.y, wv.z, wv.w};

    #pragma unroll
    for (int b = 0; b < B_DIM; b++) {
        float s    = wb[b] * c + tf;           // match reference mul-then-add
        int   k0   = __float2int_rd(s);
        float frac = s - (float)k0;
        int   k1   = k0 + 1;

        // exact k-range enforcement via weight masks (FSEL, no branch)
        float m0 = (k0 >= 0 && k0 < T_DIM) ? (1.0f - frac) : 0.0f;
        float m1 = (k1 >= 0 && k1 < T_DIM) ? frac          : 0.0f;

        // tile reads with clamped smem index (always a valid address)
        int o0 = min(max(k0 - base, 0), TILE - 1);
        int o1 = min(max(k1 - base, 0), TILE - 1);

        // store as soon as this chain resolves (coalesced per warp)
        out[b * T_DIM + t] = fmaf(m0, sx[o0], m1 * sx[o1]);
    }
}

extern "C" void kernel_launch(void* const* d_in, const int* in_sizes, int n_in,
                              void* d_out, int out_size) {
    const float4* w4 = (const float4*)d_in[0];  // [4,1] -> one float4
    const float*  x  = (const float*)d_in[1];   // [1,4096]
    float* out = (float*)d_out;                 // [4,4096,1] = 16384 floats

    const int blocks = T_DIM / BLK;             // 32
    tvp_kernel<<<blocks, BLK>>>(w4, x, out);
}